// round 3
// baseline (speedup 1.0000x reference)
#include <cuda_runtime.h>
#include <math.h>

#define DIM 384
#define TOKENS 8192
#define HID 1536
#define HEADS 6

// ---------------- scratch (device globals; no allocations allowed) ----------
__device__ float g_y[TOKENS * DIM];          // LN output (reused for LN1 & LN2)
__device__ float g_qkv[TOKENS * 3 * DIM];    // qkv projection
__device__ float g_attn[TOKENS * DIM];       // attention output [B,N,C]
__device__ float g_res[TOKENS * DIM];        // x + proj(attn)
__device__ float g_h[TOKENS * HID];          // MLP hidden

// ---------------- LayerNorm: one block (128 thr) per row of 384 -------------
__global__ void ln_kernel(const float* __restrict__ in, const float* __restrict__ w,
                          const float* __restrict__ b, float* __restrict__ out) {
    int row = blockIdx.x;
    const float* x = in + (size_t)row * DIM;
    int t = threadIdx.x;  // 128
    float v0 = x[t], v1 = x[t + 128], v2 = x[t + 256];
    float s = v0 + v1 + v2;
    float q = v0 * v0 + v1 * v1 + v2 * v2;
#pragma unroll
    for (int off = 16; off; off >>= 1) {
        s += __shfl_xor_sync(0xffffffffu, s, off);
        q += __shfl_xor_sync(0xffffffffu, q, off);
    }
    __shared__ float ss[4], sq[4];
    int wid = t >> 5, lane = t & 31;
    if (lane == 0) { ss[wid] = s; sq[wid] = q; }
    __syncthreads();
    s = ss[0] + ss[1] + ss[2] + ss[3];
    q = sq[0] + sq[1] + sq[2] + sq[3];
    float mean = s * (1.0f / DIM);
    float var = q * (1.0f / DIM) - mean * mean;
    float rstd = rsqrtf(var + 1e-5f);
    float* o = out + (size_t)row * DIM;
    o[t]       = (v0 - mean) * rstd * w[t]       + b[t];
    o[t + 128] = (v1 - mean) * rstd * w[t + 128] + b[t + 128];
    o[t + 256] = (v2 - mean) * rstd * w[t + 256] + b[t + 256];
}

// ---------------- GEMM C[M,N] = A[M,K] * B[N,K]^T (+epilogue) ---------------
// 64x64 block tile, BK=16, 256 threads, 4x4 per thread.
enum { EPI_NONE = 0, EPI_BIAS_RES = 1, EPI_GELU = 2, EPI_OUT2 = 3 };

template <int EPI>
__global__ void __launch_bounds__(256)
gemm_nt(const float* __restrict__ A, const float* __restrict__ B,
        const float* __restrict__ bias, const float* __restrict__ res,
        float* __restrict__ C, int M, int N, int K) {
    __shared__ float As[16][68];  // [k][m] (transposed)
    __shared__ float Bs[16][68];  // [k][n] (transposed)
    int bm = blockIdx.y * 64, bn = blockIdx.x * 64;
    int tid = threadIdx.x;
    int ty = tid >> 4, tx = tid & 15;
    int lr = tid >> 2;          // 0..63 row within tile
    int lc = (tid & 3) * 4;     // 0,4,8,12 k-offset
    float acc[4][4] = {};
    const float* Ap = A + (size_t)(bm + lr) * K + lc;
    const float* Bp = B + (size_t)(bn + lr) * K + lc;
    for (int k0 = 0; k0 < K; k0 += 16) {
        float4 a = *(const float4*)(Ap + k0);
        float4 bb = *(const float4*)(Bp + k0);
        __syncthreads();
        As[lc + 0][lr] = a.x;  As[lc + 1][lr] = a.y;
        As[lc + 2][lr] = a.z;  As[lc + 3][lr] = a.w;
        Bs[lc + 0][lr] = bb.x; Bs[lc + 1][lr] = bb.y;
        Bs[lc + 2][lr] = bb.z; Bs[lc + 3][lr] = bb.w;
        __syncthreads();
#pragma unroll
        for (int kk = 0; kk < 16; kk++) {
            float4 av = *(const float4*)(&As[kk][ty * 4]);
            float4 bv = *(const float4*)(&Bs[kk][tx * 4]);
            float aa[4] = {av.x, av.y, av.z, av.w};
            float bq[4] = {bv.x, bv.y, bv.z, bv.w};
#pragma unroll
            for (int i = 0; i < 4; i++)
#pragma unroll
                for (int j = 0; j < 4; j++) acc[i][j] += aa[i] * bq[j];
        }
    }
#pragma unroll
    for (int i = 0; i < 4; i++) {
        int row = bm + ty * 4 + i;
        int col0 = bn + tx * 4;
        float4 o;
        float* ov = &o.x;
#pragma unroll
        for (int j = 0; j < 4; j++) {
            float v = acc[i][j];
            int col = col0 + j;
            if (EPI == EPI_BIAS_RES) {
                v = v + bias[col] + res[(size_t)row * N + col];
            } else if (EPI == EPI_GELU) {
                v += bias[col];
                v = 0.5f * v * (1.0f + erff(v * 0.70710678118654752f));
            } else if (EPI == EPI_OUT2) {
                v = 2.0f * (v + bias[col]);
            }
            ov[j] = v;
        }
        *(float4*)(&C[(size_t)row * N + col0]) = o;
    }
}

// ---------------- Flash attention: 64-query tile per block ------------------
// qkv layout per token row (1152): [which(3)][head(6)][d(64)]
__global__ void __launch_bounds__(256)
attn_kernel(const float* __restrict__ qkv, float* __restrict__ out) {
    extern __shared__ float sm[];
    float* Qt = sm;                 // [d=64][i=64] (+pad 68) scaled Q, d-major
    float* Kt = sm + 64 * 68;       // [d=64][j=64] d-major
    float* Vs = sm + 2 * 64 * 68;   // [j=64][c=64] token-major
    float* Ps = sm + 3 * 64 * 68;   // [i=64][j=64] row-major
    int bh = blockIdx.y;
    int b = bh / HEADS, h = bh % HEADS;
    int q0 = blockIdx.x * 64;
    int tid = threadIdx.x;
    int ty = tid >> 4, tx = tid & 15;
    const size_t base = (size_t)b * 4096 * 1152 + (size_t)h * 64;
    const float* qb = qkv + base;
    const float* kb = qkv + base + 384;
    const float* vb = qkv + base + 768;
    const float scale = 0.125f;  // 64^-0.5

    for (int i = tid; i < 1024; i += 256) {
        int r = i >> 4;
        int c = (i & 15) * 4;
        float4 v = *(const float4*)(qb + (size_t)(q0 + r) * 1152 + c);
        Qt[(c + 0) * 68 + r] = v.x * scale;
        Qt[(c + 1) * 68 + r] = v.y * scale;
        Qt[(c + 2) * 68 + r] = v.z * scale;
        Qt[(c + 3) * 68 + r] = v.w * scale;
    }

    float m[4], l[4], o[4][4];
#pragma unroll
    for (int i = 0; i < 4; i++) {
        m[i] = -1e30f; l[i] = 0.0f;
#pragma unroll
        for (int j = 0; j < 4; j++) o[i][j] = 0.0f;
    }

    for (int kt = 0; kt < 64; kt++) {
        int k0 = kt * 64;
        for (int i = tid; i < 1024; i += 256) {
            int r = i >> 4;
            int c = (i & 15) * 4;
            float4 kv = *(const float4*)(kb + (size_t)(k0 + r) * 1152 + c);
            float4 vv = *(const float4*)(vb + (size_t)(k0 + r) * 1152 + c);
            Kt[(c + 0) * 68 + r] = kv.x;
            Kt[(c + 1) * 68 + r] = kv.y;
            Kt[(c + 2) * 68 + r] = kv.z;
            Kt[(c + 3) * 68 + r] = kv.w;
            *(float4*)(&Vs[r * 68 + c]) = vv;
        }
        __syncthreads();

        // S = Q K^T (this thread: rows ty*4.., cols tx*4..)
        float s[4][4] = {};
#pragma unroll 16
        for (int d = 0; d < 64; d++) {
            float4 av = *(const float4*)(&Qt[d * 68 + ty * 4]);
            float4 bv = *(const float4*)(&Kt[d * 68 + tx * 4]);
            float aa[4] = {av.x, av.y, av.z, av.w};
            float bq[4] = {bv.x, bv.y, bv.z, bv.w};
#pragma unroll
            for (int i = 0; i < 4; i++)
#pragma unroll
                for (int j = 0; j < 4; j++) s[i][j] += aa[i] * bq[j];
        }

        // online softmax
#pragma unroll
        for (int i = 0; i < 4; i++) {
            float v = fmaxf(fmaxf(s[i][0], s[i][1]), fmaxf(s[i][2], s[i][3]));
#pragma unroll
            for (int off = 1; off < 16; off <<= 1)
                v = fmaxf(v, __shfl_xor_sync(0xffffffffu, v, off));
            float mn = fmaxf(m[i], v);
            float al = __expf(m[i] - mn);
            m[i] = mn;
            float sum = 0.0f;
#pragma unroll
            for (int j = 0; j < 4; j++) {
                float p = __expf(s[i][j] - mn);
                s[i][j] = p;
                sum += p;
            }
#pragma unroll
            for (int off = 1; off < 16; off <<= 1)
                sum += __shfl_xor_sync(0xffffffffu, sum, off);
            l[i] = l[i] * al + sum;
#pragma unroll
            for (int j = 0; j < 4; j++) o[i][j] *= al;
            *(float4*)(&Ps[(ty * 4 + i) * 68 + tx * 4]) =
                make_float4(s[i][0], s[i][1], s[i][2], s[i][3]);
        }
        __syncthreads();

        // O += P V (this thread: rows ty*4.., headdim cols tx*4..)
#pragma unroll 16
        for (int kk = 0; kk < 64; kk++) {
            float4 vv = *(const float4*)(&Vs[kk * 68 + tx * 4]);
            float p0 = Ps[(ty * 4 + 0) * 68 + kk];
            float p1 = Ps[(ty * 4 + 1) * 68 + kk];
            float p2 = Ps[(ty * 4 + 2) * 68 + kk];
            float p3 = Ps[(ty * 4 + 3) * 68 + kk];
            o[0][0] += p0 * vv.x; o[0][1] += p0 * vv.y; o[0][2] += p0 * vv.z; o[0][3] += p0 * vv.w;
            o[1][0] += p1 * vv.x; o[1][1] += p1 * vv.y; o[1][2] += p1 * vv.z; o[1][3] += p1 * vv.w;
            o[2][0] += p2 * vv.x; o[2][1] += p2 * vv.y; o[2][2] += p2 * vv.z; o[2][3] += p2 * vv.w;
            o[3][0] += p3 * vv.x; o[3][1] += p3 * vv.y; o[3][2] += p3 * vv.z; o[3][3] += p3 * vv.w;
        }
        __syncthreads();
    }

    // write [B,N,C] with C = h*64 + d
#pragma unroll
    for (int i = 0; i < 4; i++) {
        float inv = 1.0f / l[i];
        int row = q0 + ty * 4 + i;
        float4 ov = make_float4(o[i][0] * inv, o[i][1] * inv, o[i][2] * inv, o[i][3] * inv);
        *(float4*)(&out[((size_t)b * 4096 + row) * DIM + h * 64 + tx * 4]) = ov;
    }
}

// ---------------- launch ----------------------------------------------------
extern "C" void kernel_launch(void* const* d_in, const int* in_sizes, int n_in,
                              void* d_out, int out_size) {
    (void)in_sizes; (void)n_in; (void)out_size;
    const float* x      = (const float*)d_in[0];
    const float* qkv_w  = (const float*)d_in[1];
    const float* proj_w = (const float*)d_in[2];
    const float* proj_b = (const float*)d_in[3];
    const float* ln1_w  = (const float*)d_in[4];
    const float* ln1_b  = (const float*)d_in[5];
    const float* ln2_w  = (const float*)d_in[6];
    const float* ln2_b  = (const float*)d_in[7];
    const float* fc1_w  = (const float*)d_in[8];
    const float* fc1_b  = (const float*)d_in[9];
    const float* fc2_w  = (const float*)d_in[10];
    const float* fc2_b  = (const float*)d_in[11];
    float* out = (float*)d_out;

    float *y, *qkvb, *attn, *res, *hbuf;
    cudaGetSymbolAddress((void**)&y, g_y);
    cudaGetSymbolAddress((void**)&qkvb, g_qkv);
    cudaGetSymbolAddress((void**)&attn, g_attn);
    cudaGetSymbolAddress((void**)&res, g_res);
    cudaGetSymbolAddress((void**)&hbuf, g_h);

    // 4 * 64 * 68 * 4 bytes = 69632 dynamic smem for the attention kernel
    cudaFuncSetAttribute(attn_kernel, cudaFuncAttributeMaxDynamicSharedMemorySize, 69632);

    // 1) LN1
    ln_kernel<<<TOKENS, 128>>>(x, ln1_w, ln1_b, y);
    // 2) qkv = y @ qkv_w^T   [8192,1152]
    gemm_nt<EPI_NONE><<<dim3(18, 128), 256>>>(y, qkv_w, nullptr, nullptr, qkvb,
                                              TOKENS, 3 * DIM, DIM);
    // 3) flash attention -> g_attn [8192,384]
    attn_kernel<<<dim3(64, 12), 256, 69632>>>(qkvb, attn);
    // 4) res = x + attn @ proj_w^T + proj_b
    gemm_nt<EPI_BIAS_RES><<<dim3(6, 128), 256>>>(attn, proj_w, proj_b, x, res,
                                                 TOKENS, DIM, DIM);
    // 5) LN2
    ln_kernel<<<TOKENS, 128>>>(res, ln2_w, ln2_b, y);
    // 6) h = gelu(y @ fc1_w^T + fc1_b)  [8192,1536]
    gemm_nt<EPI_GELU><<<dim3(24, 128), 256>>>(y, fc1_w, fc1_b, nullptr, hbuf,
                                              TOKENS, HID, DIM);
    // 7) out = 2 * (h @ fc2_w^T + fc2_b)
    gemm_nt<EPI_OUT2><<<dim3(6, 128), 256>>>(hbuf, fc2_w, fc2_b, nullptr, out,
                                             TOKENS, DIM, HID);
}

// round 4
// speedup vs baseline: 1.0013x; 1.0013x over previous
#include <cuda_runtime.h>
#include <math.h>

#define DIM 384
#define TOKENS 8192
#define HID 1536
#define HEADS 6

// ---------------- scratch (device globals; no allocations allowed) ----------
__device__ float g_y[TOKENS * DIM];          // LN output (reused for LN1 & LN2)
__device__ float g_qkv[TOKENS * 3 * DIM];    // qkv projection
__device__ float g_attn[TOKENS * DIM];       // attention output [B,N,C]
__device__ float g_res[TOKENS * DIM];        // x + proj(attn)
__device__ float g_h[TOKENS * HID];          // MLP hidden

// ---------------- LayerNorm: one block (128 thr) per row of 384 -------------
__global__ void ln_kernel(const float* __restrict__ in, const float* __restrict__ w,
                          const float* __restrict__ b, float* __restrict__ out) {
    int row = blockIdx.x;
    const float* x = in + (size_t)row * DIM;
    int t = threadIdx.x;  // 128
    float v0 = x[t], v1 = x[t + 128], v2 = x[t + 256];
    float s = v0 + v1 + v2;
    float q = v0 * v0 + v1 * v1 + v2 * v2;
#pragma unroll
    for (int off = 16; off; off >>= 1) {
        s += __shfl_xor_sync(0xffffffffu, s, off);
        q += __shfl_xor_sync(0xffffffffu, q, off);
    }
    __shared__ float ss[4], sq[4];
    int wid = t >> 5, lane = t & 31;
    if (lane == 0) { ss[wid] = s; sq[wid] = q; }
    __syncthreads();
    s = ss[0] + ss[1] + ss[2] + ss[3];
    q = sq[0] + sq[1] + sq[2] + sq[3];
    float mean = s * (1.0f / DIM);
    float var = q * (1.0f / DIM) - mean * mean;
    float rstd = rsqrtf(var + 1e-5f);
    float* o = out + (size_t)row * DIM;
    o[t]       = (v0 - mean) * rstd * w[t]       + b[t];
    o[t + 128] = (v1 - mean) * rstd * w[t + 128] + b[t + 128];
    o[t + 256] = (v2 - mean) * rstd * w[t + 256] + b[t + 256];
}

// ---------------- GEMM C[M,N] = A[M,K] * B[N,K]^T (+epilogue) ---------------
// 64x64 block tile, BK=16, 256 threads, 4x4 per thread.
enum { EPI_NONE = 0, EPI_BIAS_RES = 1, EPI_GELU = 2, EPI_OUT2 = 3 };

template <int EPI>
__global__ void __launch_bounds__(256)
gemm_nt(const float* __restrict__ A, const float* __restrict__ B,
        const float* __restrict__ bias, const float* __restrict__ res,
        float* __restrict__ C, int M, int N, int K) {
    __shared__ float As[16][68];  // [k][m] (transposed)
    __shared__ float Bs[16][68];  // [k][n] (transposed)
    int bm = blockIdx.y * 64, bn = blockIdx.x * 64;
    int tid = threadIdx.x;
    int ty = tid >> 4, tx = tid & 15;
    int lr = tid >> 2;          // 0..63 row within tile
    int lc = (tid & 3) * 4;     // 0,4,8,12 k-offset
    float acc[4][4] = {};
    const float* Ap = A + (size_t)(bm + lr) * K + lc;
    const float* Bp = B + (size_t)(bn + lr) * K + lc;
    for (int k0 = 0; k0 < K; k0 += 16) {
        float4 a = *(const float4*)(Ap + k0);
        float4 bb = *(const float4*)(Bp + k0);
        __syncthreads();
        As[lc + 0][lr] = a.x;  As[lc + 1][lr] = a.y;
        As[lc + 2][lr] = a.z;  As[lc + 3][lr] = a.w;
        Bs[lc + 0][lr] = bb.x; Bs[lc + 1][lr] = bb.y;
        Bs[lc + 2][lr] = bb.z; Bs[lc + 3][lr] = bb.w;
        __syncthreads();
#pragma unroll
        for (int kk = 0; kk < 16; kk++) {
            float4 av = *(const float4*)(&As[kk][ty * 4]);
            float4 bv = *(const float4*)(&Bs[kk][tx * 4]);
            float aa[4] = {av.x, av.y, av.z, av.w};
            float bq[4] = {bv.x, bv.y, bv.z, bv.w};
#pragma unroll
            for (int i = 0; i < 4; i++)
#pragma unroll
                for (int j = 0; j < 4; j++) acc[i][j] += aa[i] * bq[j];
        }
    }
#pragma unroll
    for (int i = 0; i < 4; i++) {
        int row = bm + ty * 4 + i;
        int col0 = bn + tx * 4;
        float4 o;
        float* ov = &o.x;
#pragma unroll
        for (int j = 0; j < 4; j++) {
            float v = acc[i][j];
            int col = col0 + j;
            if (EPI == EPI_BIAS_RES) {
                v = v + bias[col] + res[(size_t)row * N + col];
            } else if (EPI == EPI_GELU) {
                v += bias[col];
                v = 0.5f * v * (1.0f + erff(v * 0.70710678118654752f));
            } else if (EPI == EPI_OUT2) {
                v = 2.0f * (v + bias[col]);
            }
            ov[j] = v;
        }
        *(float4*)(&C[(size_t)row * N + col0]) = o;
    }
}

// ---------------- Flash attention: 64-query tile per block ------------------
// qkv layout per token row (1152): [which(3)][head(6)][d(64)]
__global__ void __launch_bounds__(256)
attn_kernel(const float* __restrict__ qkv, float* __restrict__ out) {
    extern __shared__ float sm[];
    float* Qt = sm;                 // [d=64][i=64] (+pad 68) scaled Q, d-major
    float* Kt = sm + 64 * 68;       // [d=64][j=64] d-major
    float* Vs = sm + 2 * 64 * 68;   // [j=64][c=64] token-major
    float* Ps = sm + 3 * 64 * 68;   // [i=64][j=64] row-major
    int bh = blockIdx.y;
    int b = bh / HEADS, h = bh % HEADS;
    int q0 = blockIdx.x * 64;
    int tid = threadIdx.x;
    int ty = tid >> 4, tx = tid & 15;
    const size_t base = (size_t)b * 4096 * 1152 + (size_t)h * 64;
    const float* qb = qkv + base;
    const float* kb = qkv + base + 384;
    const float* vb = qkv + base + 768;
    const float scale = 0.125f;  // 64^-0.5

    for (int i = tid; i < 1024; i += 256) {
        int r = i >> 4;
        int c = (i & 15) * 4;
        float4 v = *(const float4*)(qb + (size_t)(q0 + r) * 1152 + c);
        Qt[(c + 0) * 68 + r] = v.x * scale;
        Qt[(c + 1) * 68 + r] = v.y * scale;
        Qt[(c + 2) * 68 + r] = v.z * scale;
        Qt[(c + 3) * 68 + r] = v.w * scale;
    }

    float m[4], l[4], o[4][4];
#pragma unroll
    for (int i = 0; i < 4; i++) {
        m[i] = -1e30f; l[i] = 0.0f;
#pragma unroll
        for (int j = 0; j < 4; j++) o[i][j] = 0.0f;
    }

    for (int kt = 0; kt < 64; kt++) {
        int k0 = kt * 64;
        for (int i = tid; i < 1024; i += 256) {
            int r = i >> 4;
            int c = (i & 15) * 4;
            float4 kv = *(const float4*)(kb + (size_t)(k0 + r) * 1152 + c);
            float4 vv = *(const float4*)(vb + (size_t)(k0 + r) * 1152 + c);
            Kt[(c + 0) * 68 + r] = kv.x;
            Kt[(c + 1) * 68 + r] = kv.y;
            Kt[(c + 2) * 68 + r] = kv.z;
            Kt[(c + 3) * 68 + r] = kv.w;
            *(float4*)(&Vs[r * 68 + c]) = vv;
        }
        __syncthreads();

        // S = Q K^T (this thread: rows ty*4.., cols tx*4..)
        float s[4][4] = {};
#pragma unroll 16
        for (int d = 0; d < 64; d++) {
            float4 av = *(const float4*)(&Qt[d * 68 + ty * 4]);
            float4 bv = *(const float4*)(&Kt[d * 68 + tx * 4]);
            float aa[4] = {av.x, av.y, av.z, av.w};
            float bq[4] = {bv.x, bv.y, bv.z, bv.w};
#pragma unroll
            for (int i = 0; i < 4; i++)
#pragma unroll
                for (int j = 0; j < 4; j++) s[i][j] += aa[i] * bq[j];
        }

        // online softmax
#pragma unroll
        for (int i = 0; i < 4; i++) {
            float v = fmaxf(fmaxf(s[i][0], s[i][1]), fmaxf(s[i][2], s[i][3]));
#pragma unroll
            for (int off = 1; off < 16; off <<= 1)
                v = fmaxf(v, __shfl_xor_sync(0xffffffffu, v, off));
            float mn = fmaxf(m[i], v);
            float al = __expf(m[i] - mn);
            m[i] = mn;
            float sum = 0.0f;
#pragma unroll
            for (int j = 0; j < 4; j++) {
                float p = __expf(s[i][j] - mn);
                s[i][j] = p;
                sum += p;
            }
#pragma unroll
            for (int off = 1; off < 16; off <<= 1)
                sum += __shfl_xor_sync(0xffffffffu, sum, off);
            l[i] = l[i] * al + sum;
#pragma unroll
            for (int j = 0; j < 4; j++) o[i][j] *= al;
            *(float4*)(&Ps[(ty * 4 + i) * 68 + tx * 4]) =
                make_float4(s[i][0], s[i][1], s[i][2], s[i][3]);
        }
        __syncthreads();

        // O += P V (this thread: rows ty*4.., headdim cols tx*4..)
#pragma unroll 16
        for (int kk = 0; kk < 64; kk++) {
            float4 vv = *(const float4*)(&Vs[kk * 68 + tx * 4]);
            float p0 = Ps[(ty * 4 + 0) * 68 + kk];
            float p1 = Ps[(ty * 4 + 1) * 68 + kk];
            float p2 = Ps[(ty * 4 + 2) * 68 + kk];
            float p3 = Ps[(ty * 4 + 3) * 68 + kk];
            o[0][0] += p0 * vv.x; o[0][1] += p0 * vv.y; o[0][2] += p0 * vv.z; o[0][3] += p0 * vv.w;
            o[1][0] += p1 * vv.x; o[1][1] += p1 * vv.y; o[1][2] += p1 * vv.z; o[1][3] += p1 * vv.w;
            o[2][0] += p2 * vv.x; o[2][1] += p2 * vv.y; o[2][2] += p2 * vv.z; o[2][3] += p2 * vv.w;
            o[3][0] += p3 * vv.x; o[3][1] += p3 * vv.y; o[3][2] += p3 * vv.z; o[3][3] += p3 * vv.w;
        }
        __syncthreads();
    }

    // write [B,N,C] with C = h*64 + d
#pragma unroll
    for (int i = 0; i < 4; i++) {
        float inv = 1.0f / l[i];
        int row = q0 + ty * 4 + i;
        float4 ov = make_float4(o[i][0] * inv, o[i][1] * inv, o[i][2] * inv, o[i][3] * inv);
        *(float4*)(&out[((size_t)b * 4096 + row) * DIM + h * 64 + tx * 4]) = ov;
    }
}

// ---------------- launch ----------------------------------------------------
extern "C" void kernel_launch(void* const* d_in, const int* in_sizes, int n_in,
                              void* d_out, int out_size) {
    (void)in_sizes; (void)n_in; (void)out_size;
    const float* x      = (const float*)d_in[0];
    const float* qkv_w  = (const float*)d_in[1];
    const float* proj_w = (const float*)d_in[2];
    const float* proj_b = (const float*)d_in[3];
    const float* ln1_w  = (const float*)d_in[4];
    const float* ln1_b  = (const float*)d_in[5];
    const float* ln2_w  = (const float*)d_in[6];
    const float* ln2_b  = (const float*)d_in[7];
    const float* fc1_w  = (const float*)d_in[8];
    const float* fc1_b  = (const float*)d_in[9];
    const float* fc2_w  = (const float*)d_in[10];
    const float* fc2_b  = (const float*)d_in[11];
    float* out = (float*)d_out;

    float *y, *qkvb, *attn, *res, *hbuf;
    cudaGetSymbolAddress((void**)&y, g_y);
    cudaGetSymbolAddress((void**)&qkvb, g_qkv);
    cudaGetSymbolAddress((void**)&attn, g_attn);
    cudaGetSymbolAddress((void**)&res, g_res);
    cudaGetSymbolAddress((void**)&hbuf, g_h);

    // 4 * 64 * 68 * 4 bytes = 69632 dynamic smem for the attention kernel
    cudaFuncSetAttribute(attn_kernel, cudaFuncAttributeMaxDynamicSharedMemorySize, 69632);

    // 1) LN1
    ln_kernel<<<TOKENS, 128>>>(x, ln1_w, ln1_b, y);
    // 2) qkv = y @ qkv_w^T   [8192,1152]
    gemm_nt<EPI_NONE><<<dim3(18, 128), 256>>>(y, qkv_w, nullptr, nullptr, qkvb,
                                              TOKENS, 3 * DIM, DIM);
    // 3) flash attention -> g_attn [8192,384]
    attn_kernel<<<dim3(64, 12), 256, 69632>>>(qkvb, attn);
    // 4) res = x + attn @ proj_w^T + proj_b
    gemm_nt<EPI_BIAS_RES><<<dim3(6, 128), 256>>>(attn, proj_w, proj_b, x, res,
                                                 TOKENS, DIM, DIM);
    // 5) LN2
    ln_kernel<<<TOKENS, 128>>>(res, ln2_w, ln2_b, y);
    // 6) h = gelu(y @ fc1_w^T + fc1_b)  [8192,1536]
    gemm_nt<EPI_GELU><<<dim3(24, 128), 256>>>(y, fc1_w, fc1_b, nullptr, hbuf,
                                              TOKENS, HID, DIM);
    // 7) out = 2 * (h @ fc2_w^T + fc2_b)
    gemm_nt<EPI_OUT2><<<dim3(6, 128), 256>>>(hbuf, fc2_w, fc2_b, nullptr, out,
                                             TOKENS, DIM, HID);
}